// round 1
// baseline (speedup 1.0000x reference)
#include <cuda_runtime.h>
#include <math.h>
#include <stdint.h>

#define HDIM   1536
#define BB     4
#define SL     2048
#define NHEADS 12
#define HDH    128
#define MEMD   128
#define INNERD 6144
#define NT     (BB*SL)          // 8192 tokens
#define KW     4
#define CHUNK  64
#define NCHUNK (SL/CHUNK)       // 32
#define MT     8                // mem columns per scan block
#define QS     129              // padded smem row stride (bank-conflict-free)

// ------------------------------------------------------------------ scratch
__device__ float g_y   [(size_t)NT*HDIM];
__device__ float g_t0  [(size_t)NT*HDIM];
__device__ float g_t1  [(size_t)NT*HDIM];
__device__ float g_xh  [(size_t)NT*HDIM];
__device__ float g_h2  [(size_t)NT*HDIM];
__device__ float g_big [(size_t)NT*2*INNERD];
__device__ float g_ffn [(size_t)NT*INNERD];
__device__ float g_q   [(size_t)NT*4*HDH];
__device__ float g_k   [(size_t)NT*4*HDH];
__device__ float g_v   [(size_t)NT*4*HDH];
__device__ float g_rd  [(size_t)NT*4*HDH];
__device__ float g_mo  [(size_t)NT*4*HDH];
__device__ float g_gm  [(size_t)NT*4];
__device__ float g_hw  [(size_t)NT*NHEADS];
__device__ float g_gate[NT];

__constant__ int c_dils[NHEADS][3] = {
    {1,2,4},{1,1,1},{4,8,16},{8,16,32},{32,64,128},{64,128,256},
    {256,512,1024},{1,100,200},{1,500,1000},{1,1024,2048},{3,9,27},{5,25,125}};

__device__ __forceinline__ float sigf(float v){ return 1.f/(1.f+expf(-v)); }
__device__ __forceinline__ float geluf(float v){ return 0.5f*v*(1.f+erff(v*0.70710678118654752f)); }

// ------------------------------------------------------------ rms + gate (+router)
__global__ void __launch_bounds__(256) rms_router_kernel(
    const float* __restrict__ x, const float* __restrict__ nw,
    const float* __restrict__ gw, const float* __restrict__ gb,
    float* __restrict__ y, float* __restrict__ gate,
    const float* __restrict__ rw, const float* __restrict__ rb,
    float* __restrict__ hw)
{
    __shared__ float sy[HDIM];
    __shared__ float red[256];
    int t = blockIdx.x, tid = threadIdx.x;
    const float* xr = x + (size_t)t*HDIM;
    float ss = 0.f, gd = 0.f;
    for (int i = tid; i < HDIM; i += 256){
        float v = xr[i]; sy[i] = v; ss += v*v; gd += v*gw[i];
    }
    red[tid] = ss; __syncthreads();
    for (int s = 128; s > 0; s >>= 1){ if (tid < s) red[tid] += red[tid+s]; __syncthreads(); }
    float rs = rsqrtf(red[0]*(1.f/HDIM) + 1e-6f);
    __syncthreads();
    red[tid] = gd; __syncthreads();
    for (int s = 128; s > 0; s >>= 1){ if (tid < s) red[tid] += red[tid+s]; __syncthreads(); }
    if (tid == 0) gate[t] = sigf(red[0] + gb[0]);
    float* yr = y + (size_t)t*HDIM;
    for (int i = tid; i < HDIM; i += 256){
        float v = sy[i]*rs*nw[i]; yr[i] = v; sy[i] = v;
    }
    if (rw){
        __syncthreads();
        int warp = tid >> 5, lane = tid & 31;
        for (int r = warp; r < NHEADS; r += 8){
            float s = 0.f;
            for (int i = lane; i < HDIM; i += 32) s += sy[i]*rw[r*HDIM + i];
            #pragma unroll
            for (int o = 16; o; o >>= 1) s += __shfl_down_sync(0xffffffffu, s, o);
            if (lane == 0) hw[(size_t)t*NHEADS + r] = sigf(s + rb[r]);
        }
    }
}

// ------------------------------------------------------------ conv stack stage
__global__ void __launch_bounds__(256) convstack_kernel(
    const float* __restrict__ in, float* __restrict__ out,
    const float* __restrict__ w, const float* __restrict__ b, int dil)
{
    long idx = (long)blockIdx.x*256 + threadIdx.x;
    if (idx >= (long)NT*HDIM) return;
    int c = (int)(idx % HDIM);
    long row = idx / HDIM;
    int t = (int)(row % SL);
    float acc = b[c];
    #pragma unroll
    for (int k = 0; k < KW; k++){
        int tt = t - (KW-1-k)*dil;
        if (tt >= 0) acc += in[idx + (long)(tt - t)*HDIM] * w[c*KW + k];
    }
    out[idx] = in[idx] + geluf(acc);
}

// ------------------------------------------------------------ per-head conv stage
__global__ void __launch_bounds__(256) headconv_kernel(
    const float* __restrict__ in, float* __restrict__ out,
    const float* __restrict__ w, const float* __restrict__ b, int stage)
{
    long idx = (long)blockIdx.x*256 + threadIdx.x;
    if (idx >= (long)NT*HDIM) return;
    int d = (int)(idx & (HDH-1));
    int i = (int)((idx / HDH) % NHEADS);
    long tok = idx / HDIM;
    int t = (int)(tok % SL);
    int dil = c_dils[i][stage];
    const float* wp = w + ((i*3 + stage)*HDH + d)*KW;
    float acc = b[(i*3 + stage)*HDH + d];
    #pragma unroll
    for (int k = 0; k < KW; k++){
        int tt = t - (KW-1-k)*dil;
        if (tt >= 0) acc += in[idx + (long)(tt - t)*HDIM] * wp[k];
    }
    out[idx] = in[idx] + acc;
}

// ------------------------------------------------------------ combine heads
__global__ void __launch_bounds__(256) combine_kernel(
    const float* __restrict__ hbuf, const float* __restrict__ memout,
    const float* __restrict__ hw, float* __restrict__ out)
{
    long idx = (long)blockIdx.x*256 + threadIdx.x;
    if (idx >= (long)NT*HDIM) return;
    int d = (int)(idx & (HDH-1));
    int i = (int)((idx / HDH) % NHEADS);
    long tok = idx / HDIM;
    float v = hbuf[idx];
    if (i >= 6 && i <= 9) v += memout[(tok*4 + (i-6))*HDH + d];
    out[idx] = v * hw[tok*NHEADS + i];
}

// ------------------------------------------------------------ GLU elementwise
__global__ void __launch_bounds__(256) glu_kernel(
    const float* __restrict__ big, float* __restrict__ out, int N)
{
    long idx = (long)blockIdx.x*256 + threadIdx.x;
    if (idx >= (long)NT*N) return;
    long m = idx / N; int n = (int)(idx % N);
    float c = big[m*2L*N + n];
    float g = big[m*2L*N + N + n];
    out[idx] = c * sigf(g);
}

// ------------------------------------------------------------ memory write-gate
__global__ void __launch_bounds__(128) memgate_kernel(
    const float* __restrict__ xh, const float* __restrict__ wg,
    const float* __restrict__ bg, float* __restrict__ g)
{
    __shared__ float red[128];
    int t = blockIdx.x, tid = threadIdx.x;
    for (int h = 0; h < 4; h++){
        float v = xh[(size_t)t*HDIM + (6+h)*HDH + tid] * wg[h*HDH + tid];
        red[tid] = v; __syncthreads();
        for (int s = 64; s > 0; s >>= 1){ if (tid < s) red[tid] += red[tid+s]; __syncthreads(); }
        if (tid == 0) g[t*4 + h] = sigf(red[0] + bg[h]);
        __syncthreads();
    }
}

// ------------------------------------------------------------ memory scan
// One block per (batch, head, 8-column tile of M). 32 sequential chunks.
#define SCAN_SMEM ((64*QS*2 + 64*MT + 64 + 128*(MT+1) + 4)*4)
__global__ void __launch_bounds__(256) memscan_kernel(
    const float* __restrict__ q, const float* __restrict__ k,
    const float* __restrict__ v, const float* __restrict__ g,
    float* __restrict__ reads)
{
    extern __shared__ float smem[];
    float* sQ  = smem;                 // [64][QS]
    float* sK  = sQ + 64*QS;           // k*g, [64][QS]
    float* sV  = sK + 64*QS;           // [64][MT]
    float* sG  = sV + 64*MT;           // [64]
    float* sM  = sG + 64;              // [128][MT+1]
    float* sDec= sM + 128*(MT+1);
    int tid  = threadIdx.x;
    int mblk = blockIdx.x & 15;
    int h    = (blockIdx.x >> 4) & 3;
    int b    = blockIdx.x >> 6;
    int m0   = mblk * MT;
    for (int i = tid; i < 128*(MT+1); i += 256) sM[i] = 0.f;
    for (int c = 0; c < NCHUNK; c++){
        int tok0 = b*SL + c*CHUNK;
        __syncthreads();                               // prev update done
        if (tid < 64) sG[tid] = g[(tok0 + tid)*4 + h];
        __syncthreads();
        #pragma unroll
        for (int it = 0; it < 8; it++){
            int li = tid + it*256;
            int s  = li >> 5;
            int e4 = (li & 31) << 2;
            size_t gi = ((size_t)(tok0 + s)*4 + h)*HDH + e4;
            float4 qa = *(const float4*)(q + gi);
            float4 ka = *(const float4*)(k + gi);
            float gs = sG[s];
            int so = s*QS + e4;
            sQ[so] = qa.x; sQ[so+1] = qa.y; sQ[so+2] = qa.z; sQ[so+3] = qa.w;
            sK[so] = ka.x*gs; sK[so+1] = ka.y*gs; sK[so+2] = ka.z*gs; sK[so+3] = ka.w*gs;
        }
        if (tid < 128){
            int s = tid >> 1; int mm = (tid & 1)*4;
            float4 va = *(const float4*)(v + ((size_t)(tok0 + s)*4 + h)*HDH + m0 + mm);
            float* dv = &sV[s*MT + mm];
            dv[0]=va.x; dv[1]=va.y; dv[2]=va.z; dv[3]=va.w;
        }
        __syncthreads();
        if (tid < 32){
            float dsum = sG[tid] + sG[tid + 32];
            #pragma unroll
            for (int o = 16; o; o >>= 1) dsum += __shfl_down_sync(0xffffffffu, dsum, o);
            if (tid == 0) sDec[0] = 1.f - dsum*(1.f/64.f);
        }
        // reads = q @ M (pre-update M): thread -> (s, 2 cols)
        {
            int s  = tid & 63;
            int mi = (tid >> 6)*2;
            float a0 = 0.f, a1 = 0.f;
            const float* qr = sQ + s*QS;
            #pragma unroll 8
            for (int d = 0; d < HDH; d++){
                float qv = qr[d];
                a0 += qv * sM[d*(MT+1) + mi];
                a1 += qv * sM[d*(MT+1) + mi + 1];
            }
            size_t ro = ((size_t)(tok0 + s)*4 + h)*HDH + m0 + mi;
            reads[ro] = a0; reads[ro+1] = a1;
        }
        __syncthreads();                               // reads done before M update
        // M = decay*M + (k*g)^T v : thread -> (d, 4 cols)
        {
            int d  = tid & 127;
            int mb = (tid >> 7)*4;
            float dec = sDec[0];
            float a0 = dec*sM[d*(MT+1)+mb+0];
            float a1 = dec*sM[d*(MT+1)+mb+1];
            float a2 = dec*sM[d*(MT+1)+mb+2];
            float a3 = dec*sM[d*(MT+1)+mb+3];
            #pragma unroll 8
            for (int s = 0; s < 64; s++){
                float kgv = sK[s*QS + d];
                const float* vr = sV + s*MT + mb;
                a0 += kgv*vr[0]; a1 += kgv*vr[1]; a2 += kgv*vr[2]; a3 += kgv*vr[3];
            }
            sM[d*(MT+1)+mb+0]=a0; sM[d*(MT+1)+mb+1]=a1;
            sM[d*(MT+1)+mb+2]=a2; sM[d*(MT+1)+mb+3]=a3;
        }
    }
}

// ------------------------------------------------------------ SGEMM  C = A @ W^T (+epi)
// epi 0: C = acc (+bias)
// epi 1: C = resid + gate[row]*(acc (+bias))
// epi 2: C = A[row,col] * sigmoid(acc + bias)
__global__ void __launch_bounds__(256) sgemm_kernel(
    const float* __restrict__ A, int lda,
    const float* __restrict__ W, int ldw,
    float* C, int ldc, int K, int epi,
    const float* __restrict__ bias,
    const float* resid, const float* __restrict__ gate)
{
    __shared__ float As[16][128];
    __shared__ float Bs[16][128];
    int tid = threadIdx.x;
    int tx = tid & 15, ty = tid >> 4;
    long bm = (long)blockIdx.y * 128;
    long bn = (long)blockIdx.x * 128;
    float acc[8][8];
    #pragma unroll
    for (int i = 0; i < 8; i++)
        #pragma unroll
        for (int j = 0; j < 8; j++) acc[i][j] = 0.f;
    int lr = tid >> 2;
    int lc = (tid & 3) << 2;
    const float* Ap = A + (bm + lr)*(long)lda + lc;
    const float* Wp = W + (bn + lr)*(long)ldw + lc;
    for (int k0 = 0; k0 < K; k0 += 16){
        float4 a0 = *(const float4*)(Ap);
        float4 a1 = *(const float4*)(Ap + 64L*lda);
        float4 b0 = *(const float4*)(Wp);
        float4 b1 = *(const float4*)(Wp + 64L*ldw);
        As[lc+0][lr] = a0.x; As[lc+1][lr] = a0.y; As[lc+2][lr] = a0.z; As[lc+3][lr] = a0.w;
        As[lc+0][lr+64] = a1.x; As[lc+1][lr+64] = a1.y; As[lc+2][lr+64] = a1.z; As[lc+3][lr+64] = a1.w;
        Bs[lc+0][lr] = b0.x; Bs[lc+1][lr] = b0.y; Bs[lc+2][lr] = b0.z; Bs[lc+3][lr] = b0.w;
        Bs[lc+0][lr+64] = b1.x; Bs[lc+1][lr+64] = b1.y; Bs[lc+2][lr+64] = b1.z; Bs[lc+3][lr+64] = b1.w;
        __syncthreads();
        #pragma unroll
        for (int kk = 0; kk < 16; kk++){
            float ar[8], br[8];
            *(float4*)&ar[0] = *(const float4*)&As[kk][ty*8];
            *(float4*)&ar[4] = *(const float4*)&As[kk][ty*8+4];
            *(float4*)&br[0] = *(const float4*)&Bs[kk][tx*8];
            *(float4*)&br[4] = *(const float4*)&Bs[kk][tx*8+4];
            #pragma unroll
            for (int i = 0; i < 8; i++)
                #pragma unroll
                for (int j = 0; j < 8; j++) acc[i][j] += ar[i]*br[j];
        }
        __syncthreads();
        Ap += 16; Wp += 16;
    }
    long row0 = bm + ty*8, col0 = bn + tx*8;
    #pragma unroll
    for (int i = 0; i < 8; i++){
        long r = row0 + i;
        #pragma unroll
        for (int j = 0; j < 8; j++){
            long c = col0 + j;
            float v = acc[i][j];
            if (bias) v += bias[c];
            if (epi == 1)      v = resid[r*ldc + c] + gate[r]*v;
            else if (epi == 2) v = A[r*(long)lda + c] * sigf(v);
            C[r*ldc + c] = v;
        }
    }
}

// ------------------------------------------------------------ host side
static float* F(const void* sym){
    void* p = nullptr;
    cudaGetSymbolAddress(&p, sym);
    return (float*)p;
}

static void gemm(const float* A, int lda, const float* W, int ldw, float* C, int ldc,
                 int M, int N, int K, int epi,
                 const float* bias, const float* resid, const float* gate)
{
    dim3 g(N/128, M/128);
    sgemm_kernel<<<g, 256>>>(A, lda, W, ldw, C, ldc, K, epi, bias, resid, gate);
}

extern "C" void kernel_launch(void* const* d_in, const int* in_sizes, int n_in,
                              void* d_out, int out_size)
{
    const float* x            = (const float*)d_in[0];
    const float* norm1_w      = (const float*)d_in[1];
    const float* norm2_w      = (const float*)d_in[2];
    const float* norm3_w      = (const float*)d_in[3];
    const float* convstack_w  = (const float*)d_in[4];
    const float* convstack_b  = (const float*)d_in[5];
    const float* conv_proj_w  = (const float*)d_in[6];
    const float* conv_proj_b  = (const float*)d_in[7];
    const float* gate_proj_w  = (const float*)d_in[8];
    const float* head_router_w= (const float*)d_in[9];
    const float* head_router_b= (const float*)d_in[10];
    const float* head_conv_w  = (const float*)d_in[11];
    const float* head_conv_b  = (const float*)d_in[12];
    const float* mem_Wq       = (const float*)d_in[13];
    const float* mem_Wk       = (const float*)d_in[14];
    const float* mem_Wv       = (const float*)d_in[15];
    const float* mem_Wg_w     = (const float*)d_in[16];
    const float* mem_Wg_b     = (const float*)d_in[17];
    const float* mem_Wout     = (const float*)d_in[18];
    const float* mix_gate_w   = (const float*)d_in[19];
    const float* mix_gate_b   = (const float*)d_in[20];
    const float* mixing_w     = (const float*)d_in[21];
    const float* mixing_b     = (const float*)d_in[22];
    const float* ffn_in_w     = (const float*)d_in[23];
    const float* ffn_out_w    = (const float*)d_in[24];
    const float* conv_gate_w  = (const float*)d_in[25];
    const float* conv_gate_b  = (const float*)d_in[26];
    const float* state_gate_w = (const float*)d_in[27];
    const float* state_gate_b = (const float*)d_in[28];
    const float* ffn_gate_w   = (const float*)d_in[29];
    const float* ffn_gate_b   = (const float*)d_in[30];
    float* out = (float*)d_out;

    float* y    = F(g_y);
    float* t0   = F(g_t0);
    float* t1   = F(g_t1);
    float* xh   = F(g_xh);
    float* h2   = F(g_h2);
    float* big  = F(g_big);
    float* ffn  = F(g_ffn);
    float* qb   = F(g_q);
    float* kb   = F(g_k);
    float* vb   = F(g_v);
    float* rd   = F(g_rd);
    float* mo   = F(g_mo);
    float* gm   = F(g_gm);
    float* hw   = F(g_hw);
    float* gate = F(g_gate);

    cudaFuncSetAttribute(memscan_kernel,
                         cudaFuncAttributeMaxDynamicSharedMemorySize, SCAN_SMEM);

    const int EW = (NT*HDIM + 255)/256;
    static const int stack_dils[6] = {1,2,4,8,16,32};

    // ============ stage A: conv branch ============
    rms_router_kernel<<<NT,256>>>(x, norm1_w, conv_gate_w, conv_gate_b,
                                  y, gate, nullptr, nullptr, nullptr);
    const float* cin = y;
    float* pp[2] = {t0, t1};
    for (int j = 0; j < 6; j++){
        convstack_kernel<<<EW,256>>>(cin, pp[j&1],
                                     convstack_w + (size_t)j*HDIM*KW,
                                     convstack_b + (size_t)j*HDIM, stack_dils[j]);
        cin = pp[j&1];
    }
    gemm(cin, HDIM, conv_proj_w, HDIM, out, HDIM, NT, HDIM, HDIM, 1,
         conv_proj_b, x, gate);

    // ============ stage B: state branch ============
    rms_router_kernel<<<NT,256>>>(out, norm2_w, state_gate_w, state_gate_b,
                                  y, gate, head_router_w, head_router_b, hw);
    gemm(y, HDIM, gate_proj_w, HDIM, big, 2*HDIM, NT, 2*HDIM, HDIM, 0,
         nullptr, nullptr, nullptr);
    glu_kernel<<<EW,256>>>(big, xh, HDIM);
    memgate_kernel<<<NT,128>>>(xh, mem_Wg_w, mem_Wg_b, gm);
    for (int h = 0; h < 4; h++){
        gemm(xh + (6+h)*HDH, HDIM, mem_Wq + (size_t)h*HDH*HDH, HDH,
             qb + h*HDH, 4*HDH, NT, HDH, HDH, 0, nullptr, nullptr, nullptr);
        gemm(xh + (6+h)*HDH, HDIM, mem_Wk + (size_t)h*HDH*HDH, HDH,
             kb + h*HDH, 4*HDH, NT, HDH, HDH, 0, nullptr, nullptr, nullptr);
        gemm(xh + (6+h)*HDH, HDIM, mem_Wv + (size_t)h*MEMD*HDH, HDH,
             vb + h*HDH, 4*HDH, NT, MEMD, HDH, 0, nullptr, nullptr, nullptr);
    }
    memscan_kernel<<<BB*4*(MEMD/MT), 256, SCAN_SMEM>>>(qb, kb, vb, gm, rd);
    for (int h = 0; h < 4; h++){
        gemm(rd + h*HDH, 4*HDH, mem_Wout + (size_t)h*HDH*MEMD, MEMD,
             mo + h*HDH, 4*HDH, NT, HDH, MEMD, 0, nullptr, nullptr, nullptr);
    }
    headconv_kernel<<<EW,256>>>(xh, h2, head_conv_w, head_conv_b, 0);
    headconv_kernel<<<EW,256>>>(h2, xh, head_conv_w, head_conv_b, 1);
    headconv_kernel<<<EW,256>>>(xh, h2, head_conv_w, head_conv_b, 2);
    combine_kernel<<<EW,256>>>(h2, mo, hw, t0);
    gemm(t0, HDIM, mix_gate_w, HDIM, t1, HDIM, NT, HDIM, HDIM, 2,
         mix_gate_b, nullptr, nullptr);
    gemm(t1, HDIM, mixing_w, HDIM, out, HDIM, NT, HDIM, HDIM, 1,
         mixing_b, out, gate);

    // ============ stage C: FFN ============
    rms_router_kernel<<<NT,256>>>(out, norm3_w, ffn_gate_w, ffn_gate_b,
                                  y, gate, nullptr, nullptr, nullptr);
    gemm(y, HDIM, ffn_in_w, HDIM, big, 2*INNERD, NT, 2*INNERD, HDIM, 0,
         nullptr, nullptr, nullptr);
    glu_kernel<<<(NT*INNERD + 255)/256, 256>>>(big, ffn, INNERD);
    gemm(ffn, INNERD, ffn_out_w, INNERD, out, HDIM, NT, HDIM, INNERD, 1,
         nullptr, out, gate);
}